// round 8
// baseline (speedup 1.0000x reference)
#include <cuda_runtime.h>
#include <cstdint>

// Shapes (fixed)
#define HW     4096
#define O_DIM  256
#define K_DIM  2048          // k = c*8 + r

// Tiling
#define TM 128
#define TN 256
#define TK 64                // 8 channels per chunk
#define NCHUNK 32
#define NTHREADS 256

// smem per buffer: A 64x128 f32 (32KB) + B 64x256 f32 (64KB)
#define A_WORDS   (64 * 128)
#define B_WORDS   (64 * 256)
#define BUF_WORDS (A_WORDS + B_WORDS)          // 24576 words = 96KB
#define SMEM_BYTES (2 * BUF_WORDS * 4)         // 192KB

static __device__ __forceinline__ uint32_t f2tf32(float x) {
    uint32_t r;
    asm("cvt.rna.tf32.f32 %0, %1;" : "=r"(r) : "f"(x));
    return r;
}

static __device__ __forceinline__ void mma_tf32(float d[4], const uint32_t a[4],
                                                uint32_t b0, uint32_t b1) {
    asm volatile("mma.sync.aligned.m16n8k8.row.col.f32.tf32.tf32.f32 "
                 "{%0,%1,%2,%3}, {%4,%5,%6,%7}, {%8,%9}, {%0,%1,%2,%3};"
                 : "+f"(d[0]), "+f"(d[1]), "+f"(d[2]), "+f"(d[3])
                 : "r"(a[0]), "r"(a[1]), "r"(a[2]), "r"(a[3]), "r"(b0), "r"(b1));
}

extern __shared__ uint32_t smem[];

// Build one K-chunk. Thread roles:
//   A: row a_m (0..127), k-half a_h  -> 32 floats
//   B: n-quad n4 (0..63), channel group chh (4 ch = x0..x3), region quad rq (4 r)
// x0..x3 passed BY VALUE (no local-array indirection).
static __device__ __forceinline__
void build_chunk(uint32_t* __restrict__ As, const float* __restrict__ a_src_k,
                 int a_m, int a_h, int chh, int rq, int n4,
                 const float (*mr)[4],
                 float4 x0, float4 x1, float4 x2, float4 x3)
{
    uint32_t* Bs = As + A_WORDS;

    // ---- A copy ----
    float4 v[8];
    #pragma unroll
    for (int q = 0; q < 8; q++)
        v[q] = *(const float4*)(a_src_k + q * 4);
    #pragma unroll
    for (int q = 0; q < 8; q++) {
        const int krow = a_h * 32 + q * 4;
        As[(krow + 0) * 128 + (a_m ^ 0 )] = f2tf32(v[q].x);
        As[(krow + 1) * 128 + (a_m ^ 8 )] = f2tf32(v[q].y);
        As[(krow + 2) * 128 + (a_m ^ 16)] = f2tf32(v[q].z);
        As[(krow + 3) * 128 + (a_m ^ 24)] = f2tf32(v[q].w);
    }

    // ---- B build: 4 channels x 4 regions x 4 pixels ----
    const uint32_t colbase = (uint32_t)(n4 * 4);
    #pragma unroll
    for (int ci = 0; ci < 4; ci++) {
        const float4 xv = (ci == 0) ? x0 : (ci == 1) ? x1 : (ci == 2) ? x2 : x3;
        const int ch = chh * 4 + ci;
        #pragma unroll
        for (int j = 0; j < 4; j++) {
            uint4 y;
            y.x = f2tf32(xv.x * mr[j][0]);
            y.y = f2tf32(xv.y * mr[j][1]);
            y.z = f2tf32(xv.z * mr[j][2]);
            y.w = f2tf32(xv.w * mr[j][3]);
            const uint32_t col = colbase ^ (8u * (uint32_t)j);   // (rq*4+j)&3 == j
            *(uint4*)(Bs + (ch * 8 + rq * 4 + j) * 256 + col) = y;
        }
    }
}

__global__ __launch_bounds__(NTHREADS, 1)
void deform_mma_kernel(const float* __restrict__ mat0,
                       const float* __restrict__ mat1,
                       const float* __restrict__ mask,
                       const float* __restrict__ Alpha,
                       const int*   __restrict__ use_alpha,
                       float*       __restrict__ out)
{
    const int tid  = threadIdx.x;
    const int wid  = tid >> 5;
    const int lane = tid & 31;

    const int nt = blockIdx.x;             // 0..127
    const int b  = nt >> 4;
    const int p0 = (nt & 15) * TN;
    const int m0 = blockIdx.y * TM;

    const int wm = (wid >> 2) * 64;        // warp m-offset (0/64)
    const int wn = (wid & 3) * 64;         // warp n-offset (0..192)

    const int c_id = lane & 3;
    const int g_id = lane >> 2;
    const uint32_t xk = 8u * c_id;

    // B-build role: n-quad + (channel group, region quad)
    const int n4   = tid & 63;
    const int slot = tid >> 6;             // 0..3
    const int chh  = slot >> 1;            // channel group: ch in chh*4..+3
    const int rq   = slot & 1;             // region quad:  r  in rq*4..+3

    // per-thread alpha-scaled mask for its 4 regions (16 regs)
    float mr[4][4];
    {
        const bool ua = (use_alpha[0] != 0);
        #pragma unroll
        for (int j = 0; j < 4; j++) {
            const int r = rq * 4 + j;
            const float a = ua ? Alpha[r] : 1.0f;
            const float4 mv = *(const float4*)(mask + r * HW + p0 + n4 * 4);
            mr[j][0] = mv.x * a; mr[j][1] = mv.y * a;
            mr[j][2] = mv.z * a; mr[j][3] = mv.w * a;
        }
    }

    const int a_m = tid >> 1;
    const int a_h = tid & 1;
    const float* a_src  = mat1 + (size_t)(m0 + a_m) * K_DIM + a_h * 32;
    const float* b_src0 = mat0 + ((size_t)b * 256 + chh * 4) * HW + p0 + n4 * 4;

    float acc[4][8][4];
    #pragma unroll
    for (int mf = 0; mf < 4; mf++)
        #pragma unroll
        for (int nf = 0; nf < 8; nf++)
            #pragma unroll
            for (int x = 0; x < 4; x++) acc[mf][nf][x] = 0.0f;

    // prologue: build chunk 0
    {
        float4 x0 = *(const float4*)(b_src0 + (size_t)0 * HW);
        float4 x1 = *(const float4*)(b_src0 + (size_t)1 * HW);
        float4 x2 = *(const float4*)(b_src0 + (size_t)2 * HW);
        float4 x3 = *(const float4*)(b_src0 + (size_t)3 * HW);
        build_chunk(smem, a_src, a_m, a_h, chh, rq, n4, mr, x0, x1, x2, x3);
    }

    for (int kc = 0; kc < NCHUNK; kc++) {
        // prefetch next chunk's gmem B inputs (4 named float4 regs, live across MMA)
        float4 x0, x1, x2, x3;
        if (kc + 1 < NCHUNK) {
            const float* src = b_src0 + (size_t)(kc + 1) * 8 * HW;
            x0 = *(const float4*)(src + (size_t)0 * HW);
            x1 = *(const float4*)(src + (size_t)1 * HW);
            x2 = *(const float4*)(src + (size_t)2 * HW);
            x3 = *(const float4*)(src + (size_t)3 * HW);
        }

        __syncthreads();

        const uint32_t* As = smem + (kc & 1) * BUF_WORDS;
        const uint32_t* Bs = As + A_WORDS;

        #pragma unroll
        for (int s = 0; s < 8; s++) {
            const int k0 = s * 8 + c_id;
            uint32_t a[4][4];
            #pragma unroll
            for (int mf = 0; mf < 4; mf++) {
                const uint32_t mlo = (uint32_t)(wm + mf * 16 + g_id) ^ xk;
                const uint32_t mhi = (uint32_t)(wm + mf * 16 + g_id + 8) ^ xk;
                a[mf][0] = As[(k0    ) * 128 + mlo];
                a[mf][1] = As[(k0    ) * 128 + mhi];
                a[mf][2] = As[(k0 + 4) * 128 + mlo];
                a[mf][3] = As[(k0 + 4) * 128 + mhi];
            }
            #pragma unroll
            for (int nf = 0; nf < 8; nf++) {
                const uint32_t ncol = (uint32_t)(wn + 8 * (nf ^ c_id) + g_id);
                const uint32_t b0 = Bs[(k0    ) * 256 + ncol];
                const uint32_t b1 = Bs[(k0 + 4) * 256 + ncol];
                #pragma unroll
                for (int mf = 0; mf < 4; mf++)
                    mma_tf32(acc[mf][nf], a[mf], b0, b1);
            }
        }

        if (kc + 1 < NCHUNK)
            build_chunk(smem + ((kc + 1) & 1) * BUF_WORDS,
                        a_src + (size_t)(kc + 1) * TK,
                        a_m, a_h, chh, rq, n4, mr, x0, x1, x2, x3);
    }

    // epilogue: c0:(g,2c) c1:(g,2c+1) c2:(g+8,2c) c3:(g+8,2c+1)
    {
        const int col = p0 + wn + 2 * c_id;
        #pragma unroll
        for (int mf = 0; mf < 4; mf++) {
            const int row = m0 + wm + mf * 16 + g_id;
            float* d0 = out + ((size_t)b * O_DIM + row    ) * HW + col;
            float* d1 = out + ((size_t)b * O_DIM + row + 8) * HW + col;
            #pragma unroll
            for (int nf = 0; nf < 8; nf++) {
                *(float2*)(d0 + nf * 8) = make_float2(acc[mf][nf][0], acc[mf][nf][1]);
                *(float2*)(d1 + nf * 8) = make_float2(acc[mf][nf][2], acc[mf][nf][3]);
            }
        }
    }
}

extern "C" void kernel_launch(void* const* d_in, const int* in_sizes, int n_in,
                              void* d_out, int out_size)
{
    const float* mat0      = (const float*)d_in[0];   // [8,256,64,64]
    const float* mat1      = (const float*)d_in[1];   // [256,256,8]
    const float* mask      = (const float*)d_in[2];   // [8,64,64]
    const float* Alpha     = (const float*)d_in[3];   // [8]
    const int*   use_alpha = (const int*)  d_in[4];
    float* out = (float*)d_out;                       // [8,256,64,64] f32

    static bool attr_done = false;
    if (!attr_done) {
        cudaFuncSetAttribute(deform_mma_kernel,
                             cudaFuncAttributeMaxDynamicSharedMemorySize, SMEM_BYTES);
        attr_done = true;
    }

    dim3 grid(128, 2);   // 128 n-tiles x 2 m-tiles
    deform_mma_kernel<<<grid, NTHREADS, SMEM_BYTES>>>(mat0, mat1, mask, Alpha, use_alpha, out);
}